// round 1
// baseline (speedup 1.0000x reference)
#include <cuda_runtime.h>

// Problem constants
#define Bn   2
#define Cc   64
#define Oo   64
#define Gg   16
#define Ee   128
#define Tin  512
#define Wk   7
#define Dd   4
#define Tout 256
#define FO   64
#define PADW 520   // padded smem row: 518 real (512 + 3 + 3), padded to 520

// Scratch (static device allocations are allowed)
__device__ float  g_Q[Bn * Oo * FO * Tout];   // pooled unnormalized conv, layout [b,o,fo,t]
__device__ float  g_S1[Oo];
__device__ float  g_S2[Oo];
__device__ float2 g_ab[Oo];                    // {a, bias56}

__global__ void zero_kernel() {
    int i = threadIdx.x;
    if (i < Oo) { g_S1[i] = 0.f; g_S2[i] = 0.f; }
}

// Block = (b, g, fo).  2 * 16 * 64 = 2048 blocks, 128 threads.
// Thread (tc, oc): tc = tid>>2 in [0,32), oc = tid&3.
// Each thread computes 8 consecutive t outputs for one output channel of the group.
__global__ __launch_bounds__(128) void conv_kernel(const float* __restrict__ x,
                                                   const float* __restrict__ wgt) {
    __shared__ float xs[8][PADW];     // rows r = f2*4 + d  (f2 in {0,1}, d in {0..3})
    __shared__ float ws[8][4][7];     // [r][oc][w], raw weights
    __shared__ float bs1[4], bs2[4];  // per-block channel-stat partials

    const int bid = blockIdx.x;
    const int b   = bid >> 10;          // / 1024
    const int g   = (bid >> 6) & 15;
    const int fo  = bid & 63;
    const int tid = threadIdx.x;

    if (tid < 4) { bs1[tid] = 0.f; bs2[tid] = 0.f; }

    // ---- Load padded x rows into smem ----
    // smem index p corresponds to padded-time index; original t = p - 3.
    for (int idx = tid; idx < 8 * PADW; idx += 128) {
        int r = idx / PADW;
        int p = idx - r * PADW;
        int c = g * 4 + (r & 3);
        int f = 2 * fo + (r >> 2);
        float v = 0.f;
        int t0 = p - 3;
        if (t0 >= 0 && t0 < Tin)
            v = x[((b * Cc + c) * Ee + f) * Tin + t0];
        xs[r][p] = v;
    }
    // ---- Load weights: weight[o][d][f][w], o = g*4 + oc, f = 2*fo + f2 ----
    for (int j = tid; j < 224; j += 128) {
        int r   = j / 28;
        int rem = j - r * 28;
        int oc  = rem / 7;
        int w   = rem - oc * 7;
        int d   = r & 3;
        int f2  = r >> 2;
        int o   = g * 4 + oc;
        ws[r][oc][w] = wgt[((o * Dd + d) * Ee + (2 * fo + f2)) * Wk + w];
    }
    __syncthreads();

    // ---- Main conv: acc[t'] = sum over 8 rows, 7 taps ----
    const int tc   = tid >> 2;
    const int oc   = tid & 3;
    const int base = tc * 16;   // smem word base (16B-aligned)

    float acc[8];
#pragma unroll
    for (int i = 0; i < 8; i++) acc[i] = 0.f;

#pragma unroll
    for (int r = 0; r < 8; r++) {
        float xw[24];
        const float4* rp = reinterpret_cast<const float4*>(&xs[r][base]);
#pragma unroll
        for (int j = 0; j < 6; j++) {
            float4 v = rp[j];
            xw[4 * j + 0] = v.x; xw[4 * j + 1] = v.y;
            xw[4 * j + 2] = v.z; xw[4 * j + 3] = v.w;
        }
        float wt[7];
#pragma unroll
        for (int w = 0; w < 7; w++) wt[w] = ws[r][oc][w];
#pragma unroll
        for (int tt = 0; tt < 8; tt++)
#pragma unroll
            for (int w = 0; w < 7; w++)
                acc[tt] = fmaf(xw[2 * tt + w], wt[w], acc[tt]);
    }

    // ---- Write pooled unnormalized conv Q ----
    {
        int o = g * 4 + oc;
        int qb = ((b * Oo + o) * FO + fo) * Tout + tc * 8;
        float4 q0 = make_float4(acc[0], acc[1], acc[2], acc[3]);
        float4 q1 = make_float4(acc[4], acc[5], acc[6], acc[7]);
        *reinterpret_cast<float4*>(&g_Q[qb])     = q0;
        *reinterpret_cast<float4*>(&g_Q[qb + 4]) = q1;
    }

    // ---- Per-row parity sums -> channel-stat contributions ----
    // s1[w] = sum_t xs[2t+w], s2[w] = sum_t xs[2t+w]^2   (t = 0..255)
    // Even w sums come from even-p parity sum Pe; odd w from Po; minor boundary fixes.
    const int lane = tid & 31;
    const int warp = tid >> 5;   // 4 warps; warp handles rows {warp, warp+4}
#pragma unroll
    for (int rr = warp; rr < 8; rr += 4) {
        float pe = 0.f, po = 0.f, pe2 = 0.f, po2 = 0.f;
        for (int m = lane; m < 259; m += 32) {
            float a0 = xs[rr][2 * m];
            float a1 = xs[rr][2 * m + 1];
            pe += a0; pe2 += a0 * a0;
            po += a1; po2 += a1 * a1;
        }
#pragma unroll
        for (int off = 16; off > 0; off >>= 1) {
            pe  += __shfl_xor_sync(0xffffffffu, pe,  off);
            po  += __shfl_xor_sync(0xffffffffu, po,  off);
            pe2 += __shfl_xor_sync(0xffffffffu, pe2, off);
            po2 += __shfl_xor_sync(0xffffffffu, po2, off);
        }
        if (lane == 0) {
            float b512 = xs[rr][512], b513 = xs[rr][513], b514 = xs[rr][514];
            float b3 = xs[rr][3], b4 = xs[rr][4];
            float s1[7], s2[7];
            s1[0] = pe - b512 - b514;  s2[0] = pe2 - b512 * b512 - b514 * b514;
            s1[1] = po - b513;         s2[1] = po2 - b513 * b513;
            s1[2] = pe - b514;         s2[2] = pe2 - b514 * b514;
            s1[3] = po;                s2[3] = po2;
            s1[4] = pe;                s2[4] = pe2;
            s1[5] = po - b3;           s2[5] = po2 - b3 * b3;
            s1[6] = pe - b4;           s2[6] = pe2 - b4 * b4;
#pragma unroll
            for (int occ = 0; occ < 4; occ++) {
                float c1 = 0.f, c2 = 0.f;
#pragma unroll
                for (int w = 0; w < 7; w++) {
                    float wv = ws[rr][occ][w];
                    c1 = fmaf(wv, s1[w], c1);
                    c2 = fmaf(wv * wv, s2[w], c2);
                }
                atomicAdd(&bs1[occ], c1);
                atomicAdd(&bs2[occ], c2);
            }
        }
    }
    __syncthreads();
    if (tid < 4) {
        atomicAdd(&g_S1[g * 4 + tid], bs1[tid]);
        atomicAdd(&g_S2[g * 4 + tid], bs2[tid]);
    }
}

__global__ void finalize_kernel(const float* __restrict__ gamma,
                                const float* __restrict__ beta) {
    int o = threadIdx.x;
    if (o < Oo) {
        const float M = 1835008.f;  // B*D*E*t*W = 2*4*128*256*7
        float mean = g_S1[o] / M;
        float var  = g_S2[o] / M - mean * mean;
        float a    = gamma[o] * rsqrtf(var + 1e-5f);
        float bias = 56.f * (beta[o] - mean * a);   // 2 pooled f * D * W = 56
        g_ab[o] = make_float2(a, bias);
    }
}

// out = leaky(a[o] * Q + bias56[o]); float4 vectorized. 524288 float4 elements.
__global__ __launch_bounds__(256) void apply_kernel(float* __restrict__ out) {
    int i = blockIdx.x * 256 + threadIdx.x;           // float4 index
    int o = (i >> 12) & 63;                           // 4096 float4 per (b,o)
    float2 ab = g_ab[o];
    float4 q  = reinterpret_cast<const float4*>(g_Q)[i];
    float4 r;
    r.x = fmaf(ab.x, q.x, ab.y);
    r.y = fmaf(ab.x, q.y, ab.y);
    r.z = fmaf(ab.x, q.z, ab.y);
    r.w = fmaf(ab.x, q.w, ab.y);
    r.x = (r.x >= 0.f) ? r.x : 0.01f * r.x;
    r.y = (r.y >= 0.f) ? r.y : 0.01f * r.y;
    r.z = (r.z >= 0.f) ? r.z : 0.01f * r.z;
    r.w = (r.w >= 0.f) ? r.w : 0.01f * r.w;
    reinterpret_cast<float4*>(out)[i] = r;
}

extern "C" void kernel_launch(void* const* d_in, const int* in_sizes, int n_in,
                              void* d_out, int out_size) {
    const float* x     = (const float*)d_in[0];
    const float* wgt   = (const float*)d_in[1];
    const float* gamma = (const float*)d_in[2];
    const float* beta  = (const float*)d_in[3];

    zero_kernel<<<1, 64>>>();
    conv_kernel<<<2048, 128>>>(x, wgt);
    finalize_kernel<<<1, 64>>>(gamma, beta);
    apply_kernel<<<2048, 256>>>((float*)d_out);
}